// round 1
// baseline (speedup 1.0000x reference)
#include <cuda_runtime.h>
#include <cstdint>

#define TOKENS 8192
#define NEXP   8
#define TOPK   2
#define HID    1024
#define INTER  4096
#define CAP    2048
#define SLOTS  (NEXP*CAP)   /* 16384 */

#define BM 128
#define BN 128
#define BK 8

typedef unsigned long long ull;

// ---------------- scratch (device globals; no allocations allowed) ----------------
__device__ int   g_assign[SLOTS];                 // slot -> token (0-based)
__device__ int   g_perm[TOKENS * TOPK];           // (t,k) -> slot (0-based, clamped)
__device__ float g_affw[TOKENS * TOPK];           // (t,k) -> normalized affinity (0 if dropped)
__device__ float g_gate[(size_t)SLOTS * INTER];   // 256 MB
__device__ float g_up  [(size_t)SLOTS * INTER];   // 256 MB
__device__ float g_oute[(size_t)SLOTS * HID];     // 64 MB

// ---------------- f32x2 helpers (sm_103a packed fp32 FMA: 2x FFMA throughput) ------
__device__ __forceinline__ ull pack2(float lo, float hi) {
    ull r; asm("mov.b64 %0, {%1, %2};" : "=l"(r) : "f"(lo), "f"(hi)); return r;
}
__device__ __forceinline__ void ffma2(ull& d, ull a, ull b) {
    asm("fma.rn.f32x2 %0, %1, %2, %0;" : "+l"(d) : "l"(a), "l"(b));
}
__device__ __forceinline__ float2 unpack2(ull v) {
    float2 r; asm("mov.b64 {%0, %1}, %2;" : "=f"(r.x), "=f"(r.y) : "l"(v)); return r;
}

// ---------------- routing: exact reference semantics ------------------------------
// position_in_expert = cumsum of PRE-drop mask; drop where pos > CAP.
__global__ void route_kernel(const int* __restrict__ eidx, const float* __restrict__ aff) {
    __shared__ int s_cnt[256][NEXP];
    int tid = threadIdx.x;

    // zero assign (empty slots read token 0; their output is weighted 0)
    for (int i = tid; i < SLOTS; i += 256) g_assign[i] = 0;

    const int TPT = TOKENS / 256;  // 32 tokens per thread
    int t0 = tid * TPT;

    int cnt[NEXP];
#pragma unroll
    for (int e = 0; e < NEXP; e++) cnt[e] = 0;

    for (int t = t0; t < t0 + TPT; ++t) {
        int2 ii = ((const int2*)eidx)[t];
#pragma unroll
        for (int e = 0; e < NEXP; e++) cnt[e] += (ii.x == e) + (ii.y == e);
    }
#pragma unroll
    for (int e = 0; e < NEXP; e++) s_cnt[tid][e] = cnt[e];
    __syncthreads();

    // exclusive scan over 256 thread-chunks, one thread per expert
    if (tid < NEXP) {
        int run = 0;
        for (int i = 0; i < 256; i++) { int v = s_cnt[i][tid]; s_cnt[i][tid] = run; run += v; }
    }
    __syncthreads();

    int run[NEXP];
#pragma unroll
    for (int e = 0; e < NEXP; e++) run[e] = s_cnt[tid][e];

    for (int t = t0; t < t0 + TPT; ++t) {
        int2 ii = ((const int2*)eidx)[t];
        float a0 = 0.f, a1 = 0.f, denom = 0.f;
        int p0 = 0, p1 = 0;
#pragma unroll
        for (int e = 0; e < NEXP; e++) {
            int ce = (ii.x == e) + (ii.y == e);
            if (ce) {
                run[e] += ce;            // pre-drop cumsum (keeps advancing past capacity)
                int pos = run[e];        // 1-based inclusive
                if (pos <= CAP) {
                    float av = aff[t * NEXP + e];
                    denom += fabsf(av);
                    int slot = pos - 1 + e * CAP;
                    g_assign[slot] = t;
                    if (ii.x == e) { p0 = slot + 1; a0 = av; }
                    if (ii.y == e) { p1 = slot + 1; a1 = av; }
                }
            }
        }
        denom = fmaxf(denom, 1e-12f);
        g_perm[2 * t]     = (p0 > 0) ? p0 - 1 : 0;
        g_perm[2 * t + 1] = (p1 > 0) ? p1 - 1 : 0;
        g_affw[2 * t]     = a0 / denom;
        g_affw[2 * t + 1] = a1 / denom;
    }
}

// ---------------- GEMM core macro-free inner loop shared by both kernels ----------
// Per-thread tile: rows {ty*4..+3, 64+ty*4..+3}, cols {tx*4..+3, 64+tx*4..+3}
// Bs reads: float4 at tx*16B -> conflict-free. As reads: 2 addresses/warp -> broadcast.

__global__ __launch_bounds__(256, 2)
void gemm_gu_kernel(const float* __restrict__ X,     // (TOKENS, HID) gathered via g_assign
                    const float* __restrict__ W,     // (NEXP, HID, INTER)
                    int which)                       // 0 -> g_gate, 1 -> g_up
{
    __shared__ float As[BK][BM + 4];
    __shared__ float Bs[BK][BN];
    float* __restrict__ Y = which ? g_up : g_gate;

    const int e  = blockIdx.z;
    const int m0 = blockIdx.y * BM;
    const int n0 = blockIdx.x * BN;
    const int tid = threadIdx.x;

    const int arow = tid >> 1, acol = (tid & 1) * 4;
    const int brow = tid >> 5, bcol = (tid & 31) * 4;

    const int tok = g_assign[e * CAP + m0 + arow];
    const float* ap = X + (size_t)tok * HID + acol;
    const float* bp = W + (size_t)e * HID * INTER + (size_t)brow * INTER + n0 + bcol;

    float4 arg = *(const float4*)ap;
    float4 brg = *(const float4*)bp;

    ull acc[8][4];
#pragma unroll
    for (int i = 0; i < 8; i++)
#pragma unroll
        for (int j = 0; j < 4; j++) acc[i][j] = 0ull;

    const int tx = tid & 15, ty = tid >> 4;
    const int KT = HID / BK;

    for (int kt = 0; kt < KT; ++kt) {
        As[acol + 0][arow] = arg.x; As[acol + 1][arow] = arg.y;
        As[acol + 2][arow] = arg.z; As[acol + 3][arow] = arg.w;
        *(float4*)&Bs[brow][bcol] = brg;
        __syncthreads();
        if (kt + 1 < KT) {
            arg = *(const float4*)(ap + (kt + 1) * BK);
            brg = *(const float4*)(bp + (size_t)(kt + 1) * BK * INTER);
        }
#pragma unroll
        for (int k = 0; k < BK; k++) {
            float4 a0 = *(const float4*)&As[k][ty * 4];
            float4 a1 = *(const float4*)&As[k][64 + ty * 4];
            float4 b0 = *(const float4*)&Bs[k][tx * 4];
            float4 b1 = *(const float4*)&Bs[k][64 + tx * 4];
            ull bb[4] = { pack2(b0.x, b0.y), pack2(b0.z, b0.w),
                          pack2(b1.x, b1.y), pack2(b1.z, b1.w) };
            float av[8] = { a0.x, a0.y, a0.z, a0.w, a1.x, a1.y, a1.z, a1.w };
#pragma unroll
            for (int i = 0; i < 8; i++) {
                ull as2 = pack2(av[i], av[i]);
#pragma unroll
                for (int j = 0; j < 4; j++) ffma2(acc[i][j], as2, bb[j]);
            }
        }
        __syncthreads();
    }

#pragma unroll
    for (int i = 0; i < 8; i++) {
        int r = (i < 4) ? (ty * 4 + i) : (64 + ty * 4 + (i - 4));
        size_t base = ((size_t)(e * CAP + m0 + r)) * INTER + n0;
        float2 c0 = unpack2(acc[i][0]), c1 = unpack2(acc[i][1]);
        float2 c2 = unpack2(acc[i][2]), c3 = unpack2(acc[i][3]);
        float4 o0 = { c0.x, c0.y, c1.x, c1.y };
        float4 o1 = { c2.x, c2.y, c3.x, c3.y };
        *(float4*)&Y[base + tx * 4]      = o0;
        *(float4*)&Y[base + 64 + tx * 4] = o1;
    }
}

__device__ __forceinline__ float silu_f(float x) {
    return x * (1.0f / (1.0f + __expf(-x)));
}

__global__ __launch_bounds__(256, 2)
void gemm_down_kernel(const float* __restrict__ W)   // (NEXP, INTER, HID)
{
    __shared__ float As[BK][BM + 4];
    __shared__ float Bs[BK][BN];

    const int e  = blockIdx.z;
    const int m0 = blockIdx.y * BM;
    const int n0 = blockIdx.x * BN;
    const int tid = threadIdx.x;

    const int arow = tid >> 1, acol = (tid & 1) * 4;
    const int brow = tid >> 5, bcol = (tid & 31) * 4;

    const float* gp = g_gate + (size_t)(e * CAP + m0 + arow) * INTER + acol;
    const float* up = g_up   + (size_t)(e * CAP + m0 + arow) * INTER + acol;
    const float* bp = W + (size_t)e * INTER * HID + (size_t)brow * HID + n0 + bcol;

    float4 gg = *(const float4*)gp;
    float4 uu = *(const float4*)up;
    float4 brg = *(const float4*)bp;

    ull acc[8][4];
#pragma unroll
    for (int i = 0; i < 8; i++)
#pragma unroll
        for (int j = 0; j < 4; j++) acc[i][j] = 0ull;

    const int tx = tid & 15, ty = tid >> 4;
    const int KT = INTER / BK;

    for (int kt = 0; kt < KT; ++kt) {
        // fused activation: A = silu(gate) * up
        As[acol + 0][arow] = silu_f(gg.x) * uu.x;
        As[acol + 1][arow] = silu_f(gg.y) * uu.y;
        As[acol + 2][arow] = silu_f(gg.z) * uu.z;
        As[acol + 3][arow] = silu_f(gg.w) * uu.w;
        *(float4*)&Bs[brow][bcol] = brg;
        __syncthreads();
        if (kt + 1 < KT) {
            gg  = *(const float4*)(gp + (kt + 1) * BK);
            uu  = *(const float4*)(up + (kt + 1) * BK);
            brg = *(const float4*)(bp + (size_t)(kt + 1) * BK * HID);
        }
#pragma unroll
        for (int k = 0; k < BK; k++) {
            float4 a0 = *(const float4*)&As[k][ty * 4];
            float4 a1 = *(const float4*)&As[k][64 + ty * 4];
            float4 b0 = *(const float4*)&Bs[k][tx * 4];
            float4 b1 = *(const float4*)&Bs[k][64 + tx * 4];
            ull bb[4] = { pack2(b0.x, b0.y), pack2(b0.z, b0.w),
                          pack2(b1.x, b1.y), pack2(b1.z, b1.w) };
            float av[8] = { a0.x, a0.y, a0.z, a0.w, a1.x, a1.y, a1.z, a1.w };
#pragma unroll
            for (int i = 0; i < 8; i++) {
                ull as2 = pack2(av[i], av[i]);
#pragma unroll
                for (int j = 0; j < 4; j++) ffma2(acc[i][j], as2, bb[j]);
            }
        }
        __syncthreads();
    }

#pragma unroll
    for (int i = 0; i < 8; i++) {
        int r = (i < 4) ? (ty * 4 + i) : (64 + ty * 4 + (i - 4));
        size_t base = ((size_t)(e * CAP + m0 + r)) * HID + n0;
        float2 c0 = unpack2(acc[i][0]), c1 = unpack2(acc[i][1]);
        float2 c2 = unpack2(acc[i][2]), c3 = unpack2(acc[i][3]);
        float4 o0 = { c0.x, c0.y, c1.x, c1.y };
        float4 o1 = { c2.x, c2.y, c3.x, c3.y };
        *(float4*)&g_oute[base + tx * 4]      = o0;
        *(float4*)&g_oute[base + 64 + tx * 4] = o1;
    }
}

// ---------------- combine: out[t] = sum_k affw[t,k] * oute[perm[t,k]] --------------
__global__ void combine_kernel(float* __restrict__ out) {
    int t = blockIdx.x;
    int h = threadIdx.x * 4;
    int p0 = g_perm[2 * t], p1 = g_perm[2 * t + 1];
    float a0 = g_affw[2 * t], a1 = g_affw[2 * t + 1];
    float4 v0 = *(const float4*)(g_oute + (size_t)p0 * HID + h);
    float4 v1 = *(const float4*)(g_oute + (size_t)p1 * HID + h);
    float4 r;
    r.x = a0 * v0.x + a1 * v1.x;
    r.y = a0 * v0.y + a1 * v1.y;
    r.z = a0 * v0.z + a1 * v1.z;
    r.w = a0 * v0.w + a1 * v1.w;
    *(float4*)(out + (size_t)t * HID + h) = r;
}

// ---------------- launch ----------------------------------------------------------
extern "C" void kernel_launch(void* const* d_in, const int* in_sizes, int n_in,
                              void* d_out, int out_size) {
    const float* hidden = (const float*)d_in[0];
    const float* aff    = (const float*)d_in[1];
    const float* gate_w = (const float*)d_in[2];
    const float* up_w   = (const float*)d_in[3];
    const float* down_w = (const float*)d_in[4];
    const int*   eidx   = (const int*)d_in[5];
    float* out = (float*)d_out;

    route_kernel<<<1, 256>>>(eidx, aff);

    dim3 g_gu(INTER / BN, CAP / BM, NEXP);   // (32, 16, 8)
    gemm_gu_kernel<<<g_gu, 256>>>(hidden, gate_w, 0);
    gemm_gu_kernel<<<g_gu, 256>>>(hidden, up_w, 1);

    dim3 g_dn(HID / BN, CAP / BM, NEXP);     // (8, 16, 8)
    gemm_down_kernel<<<g_dn, 256>>>(down_w);

    combine_kernel<<<TOKENS, 256>>>(out);
}

// round 14
// speedup vs baseline: 1.1733x; 1.1733x over previous
#include <cuda_runtime.h>
#include <cuda_bf16.h>
#include <cstdint>

#define TOKENS 8192
#define NEXP   8
#define TOPK   2
#define HID    1024
#define INTER  4096
#define CAP    2048
#define SLOTS  (NEXP*CAP)   /* 16384 */

typedef unsigned long long ull;
typedef __nv_bfloat16 bf16;

// ---------------- device scratch (referenced ONLY inside device code) --------------
// Interleaved hi/lo layout: [rows][K/32][64] bf16; each 64-chunk = 32 hi | 32 lo.
__device__ int   g_assign[SLOTS];
__device__ int   g_perm[TOKENS * TOPK];
__device__ float g_affw[TOKENS * TOPK];

__device__ bf16 g_xp  [(size_t)SLOTS * 2 * HID];           // 64 MB
__device__ bf16 g_wgp [(size_t)NEXP * INTER * 2 * HID];    // 128 MB  gate^T
__device__ bf16 g_wup [(size_t)NEXP * INTER * 2 * HID];    // 128 MB  up^T
__device__ bf16 g_wdp [(size_t)NEXP * HID * 2 * INTER];    // 128 MB  down^T
__device__ bf16 g_intp[(size_t)SLOTS * 2 * INTER];         // 256 MB  silu(g)*u
__device__ float g_oute[(size_t)SLOTS * HID];              // 64 MB

// ---------------- PTX helpers (baseline sm_80-class PTX only) ---------------------
__device__ __forceinline__ uint32_t smem_to_u32(const void* p) {
    uint32_t a;
    asm("{ .reg .u64 t; cvta.to.shared.u64 t, %1; cvt.u32.u64 %0, t; }" : "=r"(a) : "l"(p));
    return a;
}
__device__ __forceinline__ void cp_async16(uint32_t saddr, const void* g) {
    asm volatile("cp.async.cg.shared.global [%0], [%1], 16;" :: "r"(saddr), "l"(g));
}
#define CP_COMMIT() asm volatile("cp.async.commit_group;" ::: "memory")
#define CP_WAIT0()  asm volatile("cp.async.wait_group 0;" ::: "memory")

#define LDM_X4(r, a) \
    asm volatile("ldmatrix.sync.aligned.m8n8.x4.shared.b16 {%0,%1,%2,%3}, [%4];" \
        : "=r"((r)[0]), "=r"((r)[1]), "=r"((r)[2]), "=r"((r)[3]) : "r"(a))

__device__ __forceinline__ void mma16816(float* c, const uint32_t* a, uint32_t b0, uint32_t b1) {
    asm volatile("mma.sync.aligned.m16n8k16.row.col.f32.bf16.bf16.f32 "
        "{%0,%1,%2,%3}, {%4,%5,%6,%7}, {%8,%9}, {%0,%1,%2,%3};"
        : "+f"(c[0]), "+f"(c[1]), "+f"(c[2]), "+f"(c[3])
        : "r"(a[0]), "r"(a[1]), "r"(a[2]), "r"(a[3]), "r"(b0), "r"(b1));
}

#define SWZ(bo) ((bo) ^ (((bo) >> 3) & 0x70))

__device__ __forceinline__ unsigned bpack(float a, float b) {
    __nv_bfloat162 t = __floats2bfloat162_rn(a, b);
    return reinterpret_cast<unsigned&>(t);
}
__device__ __forceinline__ float silu_f(float x) {
    return x * (1.0f / (1.0f + __expf(-x)));
}

// ---------------- routing (validated) ----------------------------------------------
__global__ void route_kernel(const int* __restrict__ eidx, const float* __restrict__ aff) {
    __shared__ int s_cnt[256][NEXP];
    int tid = threadIdx.x;
    for (int i = tid; i < SLOTS; i += 256) g_assign[i] = 0;
    const int TPT = TOKENS / 256;
    int t0 = tid * TPT;
    int cnt[NEXP];
#pragma unroll
    for (int e = 0; e < NEXP; e++) cnt[e] = 0;
    for (int t = t0; t < t0 + TPT; ++t) {
        int2 ii = ((const int2*)eidx)[t];
#pragma unroll
        for (int e = 0; e < NEXP; e++) cnt[e] += (ii.x == e) + (ii.y == e);
    }
#pragma unroll
    for (int e = 0; e < NEXP; e++) s_cnt[tid][e] = cnt[e];
    __syncthreads();
    if (tid < NEXP) {
        int run = 0;
        for (int i = 0; i < 256; i++) { int v = s_cnt[i][tid]; s_cnt[i][tid] = run; run += v; }
    }
    __syncthreads();
    int run[NEXP];
#pragma unroll
    for (int e = 0; e < NEXP; e++) run[e] = s_cnt[tid][e];
    for (int t = t0; t < t0 + TPT; ++t) {
        int2 ii = ((const int2*)eidx)[t];
        float a0 = 0.f, a1 = 0.f, denom = 0.f;
        int p0 = 0, p1 = 0;
#pragma unroll
        for (int e = 0; e < NEXP; e++) {
            int ce = (ii.x == e) + (ii.y == e);
            if (ce) {
                run[e] += ce;
                int pos = run[e];
                if (pos <= CAP) {
                    float av = aff[t * NEXP + e];
                    denom += fabsf(av);
                    int slot = pos - 1 + e * CAP;
                    g_assign[slot] = t;
                    if (ii.x == e) { p0 = slot + 1; a0 = av; }
                    if (ii.y == e) { p1 = slot + 1; a1 = av; }
                }
            }
        }
        denom = fmaxf(denom, 1e-12f);
        g_perm[2 * t]     = (p0 > 0) ? p0 - 1 : 0;
        g_perm[2 * t + 1] = (p1 > 0) ? p1 - 1 : 0;
        g_affw[2 * t]     = a0 / denom;
        g_affw[2 * t + 1] = a1 / denom;
    }
}

// ---------------- prep: gather + split (validated: F0 clear) -----------------------
__global__ void gather_split_kernel(const float* __restrict__ X) {
    int s = blockIdx.x;
    int tok = g_assign[s];
    int i = threadIdx.x;
    float4 v = ((const float4*)(X + (size_t)tok * HID))[i];
    int k0 = i * 4;
    bf16* base = g_xp + (size_t)s * 2 * HID + (k0 >> 5) * 64 + (k0 & 31);
    float vv[4] = { v.x, v.y, v.z, v.w };
    float hf[4], lf[4];
#pragma unroll
    for (int j = 0; j < 4; j++) {
        bf16 h = __float2bfloat16(vv[j]);
        hf[j] = __bfloat162float(h);
        lf[j] = vv[j] - hf[j];
    }
    uint2 vh = { bpack(hf[0], hf[1]), bpack(hf[2], hf[3]) };
    uint2 vl = { bpack(lf[0], lf[1]), bpack(lf[2], lf[3]) };
    *(uint2*)(base)      = vh;
    *(uint2*)(base + 32) = vl;
}

// ---------------- prep: transpose + split (FIXED: output selected in-device) -------
// in: W [e][K_in][N_in] fp32; out: [e][N_in][K_in/32][64] bf16 (hi|lo)
__global__ void transpose_split_kernel(const float* __restrict__ W,
                                       int which, int K_in, int N_in) {
    bf16* __restrict__ out = (which == 0) ? g_wgp : (which == 1) ? g_wup : g_wdp;
    __shared__ float t[32][33];
    int e = blockIdx.z;
    int n0 = blockIdx.x * 32, k0 = blockIdx.y * 32;
    size_t ibase = (size_t)e * K_in * N_in;
    size_t obase = (size_t)e * N_in * 2 * K_in;
    int tx = threadIdx.x & 31, ty = threadIdx.x >> 5;
#pragma unroll
    for (int r = 0; r < 4; r++) {
        int row = ty + r * 8;
        t[row][tx] = W[ibase + (size_t)(k0 + row) * N_in + n0 + tx];
    }
    __syncthreads();
#pragma unroll
    for (int r = 0; r < 4; r++) {
        int nrow = ty + r * 8;
        float v = t[tx][nrow];
        bf16 h = __float2bfloat16(v);
        size_t o = obase + (size_t)(n0 + nrow) * 2 * K_in + (k0 >> 5) * 64 + tx;
        out[o]      = h;
        out[o + 32] = __float2bfloat16(v - __bfloat162float(h));
    }
}

// ---------------- loader: ROWS x 128B row-chunks, SW128 ---------------------------
template<int ROWS>
__device__ __forceinline__ void tile_async(uint32_t dst, const bf16* src,
                                           int row_stride_elems, int tid) {
#pragma unroll
    for (int j = 0; j < ROWS * 8 / 256; j++) {
        int idx = tid + j * 256;
        int row = idx >> 3, c = (idx & 7) * 16;
        cp_async16(dst + SWZ(row * 128 + c),
                   (const char*)src + (size_t)row * row_stride_elems * 2 + c);
    }
}

// ---------------- fused gate+up GEMM (HMMA, 3xBF16 split) -------------------------
// CTA tile: M=128 x N=64. Static smem 32KB: A 16KB | G 8KB | U 8KB. k-step 32/iter.
__global__ __launch_bounds__(256) void gemm_gu_mma() {
    __shared__ char smem[32768];
    const uint32_t sb = smem_to_u32(smem);
    const uint32_t sbA = sb, sbG = sb + 16384, sbU = sb + 24576;
    const int tid = threadIdx.x, wid = tid >> 5, lane = tid & 31;
    const int nb = blockIdx.x;            // n0 = nb*64 in INTER
    const int mb = blockIdx.y;            // m0 = mb*128 slots
    const int e = mb >> 4;

    const bf16* aP = g_xp + (size_t)mb * 128 * (2 * HID);
    const size_t wo = ((size_t)e * INTER + (size_t)nb * 64) * (2 * HID);
    const bf16* gP = g_wgp + wo;
    const bf16* uP = g_wup + wo;

    float accg[2][4][4] = {}, accu[2][4][4] = {};
    const int wm = wid & 3, wn = wid >> 2;
    const int rsel = lane & 15;
    const int csel = ((lane >> 4) << 4);

    const int KT = HID / 32;  // 32
    for (int kt = 0; kt < KT; ++kt) {
        __syncthreads();
        tile_async<128>(sbA, aP + kt * 64, 2 * HID, tid);
        tile_async<64>(sbG, gP + kt * 64, 2 * HID, tid);
        tile_async<64>(sbU, uP + kt * 64, 2 * HID, tid);
        CP_COMMIT(); CP_WAIT0();
        __syncthreads();
#pragma unroll
        for (int ks = 0; ks < 2; ks++) {
            const int ch = ks * 32 + csel;   // hi cols; lo at +64
            uint32_t ah[2][4], al[2][4];
#pragma unroll
            for (int mt = 0; mt < 2; mt++) {
                uint32_t ro = (wm * 32 + mt * 16 + rsel) * 128;
                LDM_X4(ah[mt], sbA + SWZ(ro + ch));
                LDM_X4(al[mt], sbA + SWZ(ro + ch + 64));
            }
#pragma unroll
            for (int g = 0; g < 2; g++) {
                uint32_t ro = (wn * 32 + g * 16 + rsel) * 128;
                uint32_t bgh[4], bgl[4], buh[4], bul[4];
                LDM_X4(bgh, sbG + SWZ(ro + ch));
                LDM_X4(bgl, sbG + SWZ(ro + ch + 64));
                LDM_X4(buh, sbU + SWZ(ro + ch));
                LDM_X4(bul, sbU + SWZ(ro + ch + 64));
#pragma unroll
                for (int mt = 0; mt < 2; mt++)
#pragma unroll
                for (int t = 0; t < 2; t++) {
                    const int nt = g * 2 + t;
                    mma16816(accg[mt][nt], ah[mt], bgh[t], bgh[t + 2]);
                    mma16816(accg[mt][nt], ah[mt], bgl[t], bgl[t + 2]);
                    mma16816(accg[mt][nt], al[mt], bgh[t], bgh[t + 2]);
                    mma16816(accu[mt][nt], ah[mt], buh[t], buh[t + 2]);
                    mma16816(accu[mt][nt], ah[mt], bul[t], bul[t + 2]);
                    mma16816(accu[mt][nt], al[mt], buh[t], buh[t + 2]);
                }
            }
        }
    }

    // epilogue: act = silu(g)*u -> interleaved hi/lo for the down GEMM
#pragma unroll
    for (int mt = 0; mt < 2; mt++)
#pragma unroll
    for (int g = 0; g < 2; g++)
#pragma unroll
    for (int t = 0; t < 2; t++)
#pragma unroll
    for (int h = 0; h < 2; h++) {
        const int nt = g * 2 + t;
        int row = mb * 128 + wm * 32 + mt * 16 + (lane >> 2) + h * 8;
        int col = nb * 64 + wn * 32 + g * 16 + t * 8 + (lane & 3) * 2;
        float g0 = accg[mt][nt][h * 2], g1 = accg[mt][nt][h * 2 + 1];
        float u0 = accu[mt][nt][h * 2], u1 = accu[mt][nt][h * 2 + 1];
        float a0 = silu_f(g0) * u0, a1 = silu_f(g1) * u1;
        bf16 h0 = __float2bfloat16(a0), h1 = __float2bfloat16(a1);
        float hf0 = __bfloat162float(h0), hf1 = __bfloat162float(h1);
        size_t o = (size_t)row * (2 * INTER) + (size_t)((col >> 5) * 64 + (col & 31));
        *(unsigned*)&g_intp[o]      = bpack(hf0, hf1);
        *(unsigned*)&g_intp[o + 32] = bpack(a0 - hf0, a1 - hf1);
    }
}

// ---------------- down GEMM (HMMA, 3xBF16 split) ----------------------------------
// CTA tile: M=128 x N=128. Static smem 32KB: A 16KB | B 16KB. K = INTER.
__global__ __launch_bounds__(256) void gemm_dn_mma() {
    __shared__ char smem[32768];
    const uint32_t sb = smem_to_u32(smem);
    const uint32_t sbA = sb, sbB = sb + 16384;
    const int tid = threadIdx.x, wid = tid >> 5, lane = tid & 31;
    const int nb = blockIdx.x;            // n0 = nb*128 in HID
    const int mb = blockIdx.y;
    const int e = mb >> 4;

    const bf16* aP = g_intp + (size_t)mb * 128 * (2 * INTER);
    const bf16* bP = g_wdp + ((size_t)e * HID + (size_t)nb * 128) * (2 * INTER);

    float acc[2][8][4] = {};
    const int wm = wid & 3, wn = wid >> 2;
    const int rsel = lane & 15;
    const int csel = ((lane >> 4) << 4);

    const int KT = INTER / 32;  // 128
#pragma unroll 1
    for (int kt = 0; kt < KT; ++kt) {
        __syncthreads();
        tile_async<128>(sbA, aP + kt * 64, 2 * INTER, tid);
        tile_async<128>(sbB, bP + kt * 64, 2 * INTER, tid);
        CP_COMMIT(); CP_WAIT0();
        __syncthreads();
#pragma unroll
        for (int ks = 0; ks < 2; ks++) {
            const int ch = ks * 32 + csel;
            uint32_t ah[2][4], al[2][4];
#pragma unroll
            for (int mt = 0; mt < 2; mt++) {
                uint32_t ro = (wm * 32 + mt * 16 + rsel) * 128;
                LDM_X4(ah[mt], sbA + SWZ(ro + ch));
                LDM_X4(al[mt], sbA + SWZ(ro + ch + 64));
            }
#pragma unroll
            for (int g = 0; g < 4; g++) {
                uint32_t ro = (wn * 64 + g * 16 + rsel) * 128;
                uint32_t bh[4], bl[4];
                LDM_X4(bh, sbB + SWZ(ro + ch));
                LDM_X4(bl, sbB + SWZ(ro + ch + 64));
#pragma unroll
                for (int mt = 0; mt < 2; mt++)
#pragma unroll
                for (int t = 0; t < 2; t++) {
                    const int nt = g * 2 + t;
                    mma16816(acc[mt][nt], ah[mt], bh[t], bh[t + 2]);
                    mma16816(acc[mt][nt], ah[mt], bl[t], bl[t + 2]);
                    mma16816(acc[mt][nt], al[mt], bh[t], bh[t + 2]);
                }
            }
        }
    }

#pragma unroll
    for (int mt = 0; mt < 2; mt++)
#pragma unroll
    for (int nt = 0; nt < 8; nt++)
#pragma unroll
    for (int h = 0; h < 2; h++) {
        int row = mb * 128 + wm * 32 + mt * 16 + (lane >> 2) + h * 8;
        int col = nb * 128 + wn * 64 + nt * 8 + (lane & 3) * 2;
        float2 v = { acc[mt][nt][h * 2], acc[mt][nt][h * 2 + 1] };
        *(float2*)&g_oute[(size_t)row * HID + col] = v;
    }
}

// ---------------- combine (validated) ----------------------------------------------
__global__ void combine_kernel(float* __restrict__ out) {
    int t = blockIdx.x;
    int h = threadIdx.x * 4;
    int p0 = g_perm[2 * t], p1 = g_perm[2 * t + 1];
    float a0 = g_affw[2 * t], a1 = g_affw[2 * t + 1];
    float4 v0 = *(const float4*)(g_oute + (size_t)p0 * HID + h);
    float4 v1 = *(const float4*)(g_oute + (size_t)p1 * HID + h);
    float4 r;
    r.x = a0 * v0.x + a1 * v1.x;
    r.y = a0 * v0.y + a1 * v1.y;
    r.z = a0 * v0.z + a1 * v1.z;
    r.w = a0 * v0.w + a1 * v1.w;
    *(float4*)(out + (size_t)t * HID + h) = r;
}

// ---------------- launch ------------------------------------------------------------
// NOTE: no kernel argument anywhere is a __device__ symbol address (GB300 ATS makes
// that a SILENT write to host memory — root cause of rounds 3-11).
extern "C" void kernel_launch(void* const* d_in, const int* in_sizes, int n_in,
                              void* d_out, int out_size) {
    const float* hidden = (const float*)d_in[0];
    const float* aff    = (const float*)d_in[1];
    const float* gate_w = (const float*)d_in[2];
    const float* up_w   = (const float*)d_in[3];
    const float* down_w = (const float*)d_in[4];
    const int*   eidx   = (const int*)d_in[5];
    float* out = (float*)d_out;

    route_kernel<<<1, 256>>>(eidx, aff);
    gather_split_kernel<<<SLOTS, 256>>>(hidden);
    transpose_split_kernel<<<dim3(INTER / 32, HID / 32, NEXP), 256>>>(gate_w, 0, HID, INTER);
    transpose_split_kernel<<<dim3(INTER / 32, HID / 32, NEXP), 256>>>(up_w,   1, HID, INTER);
    transpose_split_kernel<<<dim3(HID / 32, INTER / 32, NEXP), 256>>>(down_w, 2, INTER, HID);

    gemm_gu_mma<<<dim3(INTER / 64, SLOTS / 128), 256>>>();
    gemm_dn_mma<<<dim3(HID / 128, SLOTS / 128), 256>>>();

    combine_kernel<<<TOKENS, 256>>>(out);
}

// round 17
// speedup vs baseline: 2.4757x; 2.1101x over previous
#include <cuda_runtime.h>
#include <cuda_bf16.h>
#include <cstdint>

#define TOKENS 8192
#define NEXP   8
#define TOPK   2
#define HID    1024
#define INTER  4096
#define CAP    2048
#define SLOTS  (NEXP*CAP)   /* 16384 */

typedef unsigned long long ull;
typedef __nv_bfloat16 bf16;

// ---------------- device scratch (referenced ONLY inside device code!) -------------
// PITFALL (GB300/ATS): passing a __device__ symbol address as a kernel argument from
// host code silently writes to HOST memory. All globals below are only named in
// device code.
__device__ int   g_assign[SLOTS];
__device__ int   g_perm[TOKENS * TOPK];
__device__ float g_affw[TOKENS * TOPK];

__device__ bf16 g_xp  [(size_t)SLOTS * 2 * HID];
__device__ bf16 g_wgp [(size_t)NEXP * INTER * 2 * HID];
__device__ bf16 g_wup [(size_t)NEXP * INTER * 2 * HID];
__device__ bf16 g_wdp [(size_t)NEXP * HID * 2 * INTER];
__device__ bf16 g_intp[(size_t)SLOTS * 2 * INTER];
__device__ float g_oute[(size_t)SLOTS * HID];

// ---------------- PTX helpers ------------------------------------------------------
__device__ __forceinline__ uint32_t smem_to_u32(const void* p) {
    uint32_t a;
    asm("{ .reg .u64 t; cvta.to.shared.u64 t, %1; cvt.u32.u64 %0, t; }" : "=r"(a) : "l"(p));
    return a;
}
__device__ __forceinline__ void cp_async16(uint32_t saddr, const void* g) {
    asm volatile("cp.async.cg.shared.global [%0], [%1], 16;" :: "r"(saddr), "l"(g));
}
#define CP_COMMIT() asm volatile("cp.async.commit_group;" ::: "memory")
#define CP_WAIT0()  asm volatile("cp.async.wait_group 0;" ::: "memory")
#define CP_WAIT1()  asm volatile("cp.async.wait_group 1;" ::: "memory")

#define LDM_X4(r, a) \
    asm volatile("ldmatrix.sync.aligned.m8n8.x4.shared.b16 {%0,%1,%2,%3}, [%4];" \
        : "=r"((r)[0]), "=r"((r)[1]), "=r"((r)[2]), "=r"((r)[3]) : "r"(a))

__device__ __forceinline__ void mma16816(float* c, const uint32_t* a, uint32_t b0, uint32_t b1) {
    asm volatile("mma.sync.aligned.m16n8k16.row.col.f32.bf16.bf16.f32 "
        "{%0,%1,%2,%3}, {%4,%5,%6,%7}, {%8,%9}, {%0,%1,%2,%3};"
        : "+f"(c[0]), "+f"(c[1]), "+f"(c[2]), "+f"(c[3])
        : "r"(a[0]), "r"(a[1]), "r"(a[2]), "r"(a[3]), "r"(b0), "r"(b1));
}

#define SWZ(bo) ((bo) ^ (((bo) >> 3) & 0x70))

__device__ __forceinline__ unsigned bpack(float a, float b) {
    __nv_bfloat162 t = __floats2bfloat162_rn(a, b);
    return reinterpret_cast<unsigned&>(t);
}
__device__ __forceinline__ float silu_f(float x) {
    return x * (1.0f / (1.0f + __expf(-x)));
}

// ---------------- routing (validated) ----------------------------------------------
__global__ void route_kernel(const int* __restrict__ eidx, const float* __restrict__ aff) {
    __shared__ int s_cnt[256][NEXP];
    int tid = threadIdx.x;
    for (int i = tid; i < SLOTS; i += 256) g_assign[i] = 0;
    const int TPT = TOKENS / 256;
    int t0 = tid * TPT;
    int cnt[NEXP];
#pragma unroll
    for (int e = 0; e < NEXP; e++) cnt[e] = 0;
    for (int t = t0; t < t0 + TPT; ++t) {
        int2 ii = ((const int2*)eidx)[t];
#pragma unroll
        for (int e = 0; e < NEXP; e++) cnt[e] += (ii.x == e) + (ii.y == e);
    }
#pragma unroll
    for (int e = 0; e < NEXP; e++) s_cnt[tid][e] = cnt[e];
    __syncthreads();
    if (tid < NEXP) {
        int run = 0;
        for (int i = 0; i < 256; i++) { int v = s_cnt[i][tid]; s_cnt[i][tid] = run; run += v; }
    }
    __syncthreads();
    int run[NEXP];
#pragma unroll
    for (int e = 0; e < NEXP; e++) run[e] = s_cnt[tid][e];
    for (int t = t0; t < t0 + TPT; ++t) {
        int2 ii = ((const int2*)eidx)[t];
        float a0 = 0.f, a1 = 0.f, denom = 0.f;
        int p0 = 0, p1 = 0;
#pragma unroll
        for (int e = 0; e < NEXP; e++) {
            int ce = (ii.x == e) + (ii.y == e);
            if (ce) {
                run[e] += ce;
                int pos = run[e];
                if (pos <= CAP) {
                    float av = aff[t * NEXP + e];
                    denom += fabsf(av);
                    int slot = pos - 1 + e * CAP;
                    g_assign[slot] = t;
                    if (ii.x == e) { p0 = slot + 1; a0 = av; }
                    if (ii.y == e) { p1 = slot + 1; a1 = av; }
                }
            }
        }
        denom = fmaxf(denom, 1e-12f);
        g_perm[2 * t]     = (p0 > 0) ? p0 - 1 : 0;
        g_perm[2 * t + 1] = (p1 > 0) ? p1 - 1 : 0;
        g_affw[2 * t]     = a0 / denom;
        g_affw[2 * t + 1] = a1 / denom;
    }
}

// ---------------- prep (validated) --------------------------------------------------
__global__ void gather_split_kernel(const float* __restrict__ X) {
    int s = blockIdx.x;
    int tok = g_assign[s];
    int i = threadIdx.x;
    float4 v = ((const float4*)(X + (size_t)tok * HID))[i];
    int k0 = i * 4;
    bf16* base = g_xp + (size_t)s * 2 * HID + (k0 >> 5) * 64 + (k0 & 31);
    float vv[4] = { v.x, v.y, v.z, v.w };
    float hf[4], lf[4];
#pragma unroll
    for (int j = 0; j < 4; j++) {
        bf16 h = __float2bfloat16(vv[j]);
        hf[j] = __bfloat162float(h);
        lf[j] = vv[j] - hf[j];
    }
    uint2 vh = { bpack(hf[0], hf[1]), bpack(hf[2], hf[3]) };
    uint2 vl = { bpack(lf[0], lf[1]), bpack(lf[2], lf[3]) };
    *(uint2*)(base)      = vh;
    *(uint2*)(base + 32) = vl;
}

__global__ void transpose_split_kernel(const float* __restrict__ W,
                                       int which, int K_in, int N_in) {
    bf16* __restrict__ out = (which == 0) ? g_wgp : (which == 1) ? g_wup : g_wdp;
    __shared__ float t[32][33];
    int e = blockIdx.z;
    int n0 = blockIdx.x * 32, k0 = blockIdx.y * 32;
    size_t ibase = (size_t)e * K_in * N_in;
    size_t obase = (size_t)e * N_in * 2 * K_in;
    int tx = threadIdx.x & 31, ty = threadIdx.x >> 5;
#pragma unroll
    for (int r = 0; r < 4; r++) {
        int row = ty + r * 8;
        t[row][tx] = W[ibase + (size_t)(k0 + row) * N_in + n0 + tx];
    }
    __syncthreads();
#pragma unroll
    for (int r = 0; r < 4; r++) {
        int nrow = ty + r * 8;
        float v = t[tx][nrow];
        bf16 h = __float2bfloat16(v);
        size_t o = obase + (size_t)(n0 + nrow) * 2 * K_in + (k0 >> 5) * 64 + tx;
        out[o]      = h;
        out[o + 32] = __float2bfloat16(v - __bfloat162float(h));
    }
}

// ---------------- loader -----------------------------------------------------------
template<int ROWS>
__device__ __forceinline__ void tile_async(uint32_t dst, const bf16* src,
                                           int row_stride_elems, int tid) {
#pragma unroll
    for (int j = 0; j < ROWS * 8 / 256; j++) {
        int idx = tid + j * 256;
        int row = idx >> 3, c = (idx & 7) * 16;
        cp_async16(dst + SWZ(row * 128 + c),
                   (const char*)src + (size_t)row * row_stride_elems * 2 + c);
    }
}

// =========================== GU compute + epilogue (shared) ========================
struct GuAcc { float g[2][4][4]; float u[2][4][4]; };

__device__ __forceinline__ void gu_compute(GuAcc& A, uint32_t sbA, uint32_t sbG,
                                           uint32_t sbU, int wm, int wn,
                                           int rsel, int csel) {
#pragma unroll
    for (int ks = 0; ks < 2; ks++) {
        const int ch = ks * 32 + csel;
        uint32_t ah[2][4], al[2][4];
#pragma unroll
        for (int mt = 0; mt < 2; mt++) {
            uint32_t ro = (wm * 32 + mt * 16 + rsel) * 128;
            LDM_X4(ah[mt], sbA + SWZ(ro + ch));
            LDM_X4(al[mt], sbA + SWZ(ro + ch + 64));
        }
#pragma unroll
        for (int g = 0; g < 2; g++) {
            uint32_t ro = (wn * 32 + g * 16 + rsel) * 128;
            uint32_t bgh[4], bgl[4], buh[4], bul[4];
            LDM_X4(bgh, sbG + SWZ(ro + ch));
            LDM_X4(bgl, sbG + SWZ(ro + ch + 64));
            LDM_X4(buh, sbU + SWZ(ro + ch));
            LDM_X4(bul, sbU + SWZ(ro + ch + 64));
#pragma unroll
            for (int mt = 0; mt < 2; mt++)
#pragma unroll
            for (int t = 0; t < 2; t++) {
                const int nt = g * 2 + t;
                mma16816(A.g[mt][nt], ah[mt], bgh[t], bgh[t + 2]);
                mma16816(A.g[mt][nt], ah[mt], bgl[t], bgl[t + 2]);
                mma16816(A.g[mt][nt], al[mt], bgh[t], bgh[t + 2]);
                mma16816(A.u[mt][nt], ah[mt], buh[t], buh[t + 2]);
                mma16816(A.u[mt][nt], ah[mt], bul[t], bul[t + 2]);
                mma16816(A.u[mt][nt], al[mt], buh[t], buh[t + 2]);
            }
        }
    }
}

__device__ __forceinline__ void gu_epilogue(GuAcc& A, int mb, int nb, int wm, int wn, int lane) {
#pragma unroll
    for (int mt = 0; mt < 2; mt++)
#pragma unroll
    for (int g = 0; g < 2; g++)
#pragma unroll
    for (int t = 0; t < 2; t++)
#pragma unroll
    for (int h = 0; h < 2; h++) {
        const int nt = g * 2 + t;
        int row = mb * 128 + wm * 32 + mt * 16 + (lane >> 2) + h * 8;
        int col = nb * 64 + wn * 32 + g * 16 + t * 8 + (lane & 3) * 2;
        float g0 = A.g[mt][nt][h * 2], g1 = A.g[mt][nt][h * 2 + 1];
        float u0 = A.u[mt][nt][h * 2], u1 = A.u[mt][nt][h * 2 + 1];
        float a0 = silu_f(g0) * u0, a1 = silu_f(g1) * u1;
        bf16 h0 = __float2bfloat16(a0), h1 = __float2bfloat16(a1);
        float hf0 = __bfloat162float(h0), hf1 = __bfloat162float(h1);
        size_t o = (size_t)row * (2 * INTER) + (size_t)((col >> 5) * 64 + (col & 31));
        *(unsigned*)&g_intp[o]      = bpack(hf0, hf1);
        *(unsigned*)&g_intp[o + 32] = bpack(a0 - hf0, a1 - hf1);
    }
}

// ---- pipelined gate+up (3-stage, 96KB dynamic smem) ----
#define GU_STG 32768
__global__ __launch_bounds__(256) void gemm_gu_pipe() {
    extern __shared__ char smem[];
    const uint32_t sb = smem_to_u32(smem);
    const int tid = threadIdx.x, wid = tid >> 5, lane = tid & 31;
    const int nb = blockIdx.x, mb = blockIdx.y;
    const int e = mb >> 4;

    const bf16* aP = g_xp + (size_t)mb * 128 * (2 * HID);
    const size_t wo = ((size_t)e * INTER + (size_t)nb * 64) * (2 * HID);
    const bf16* gP = g_wgp + wo;
    const bf16* uP = g_wup + wo;

    GuAcc A = {};
    const int wm = wid & 3, wn = wid >> 2;
    const int rsel = lane & 15, csel = ((lane >> 4) << 4);

    auto load_stage = [&](int kt) {
        uint32_t base = sb + (kt % 3) * GU_STG;
        tile_async<128>(base,          aP + kt * 64, 2 * HID, tid);
        tile_async<64>(base + 16384,   gP + kt * 64, 2 * HID, tid);
        tile_async<64>(base + 24576,   uP + kt * 64, 2 * HID, tid);
        CP_COMMIT();
    };

    const int KT = HID / 32;  // 32
    load_stage(0);
    load_stage(1);
    for (int kt = 0; kt < KT; ++kt) {
        CP_WAIT1();
        __syncthreads();
        if (kt + 2 < KT) load_stage(kt + 2);
        uint32_t base = sb + (kt % 3) * GU_STG;
        gu_compute(A, base, base + 16384, base + 24576, wm, wn, rsel, csel);
    }
    gu_epilogue(A, mb, nb, wm, wn, lane);
}

// ---- fallback single-stage gate+up (passing R14 version, static smem) ----
__global__ __launch_bounds__(256) void gemm_gu_mma() {
    __shared__ char smem[32768];
    const uint32_t sb = smem_to_u32(smem);
    const int tid = threadIdx.x, wid = tid >> 5, lane = tid & 31;
    const int nb = blockIdx.x, mb = blockIdx.y;
    const int e = mb >> 4;

    const bf16* aP = g_xp + (size_t)mb * 128 * (2 * HID);
    const size_t wo = ((size_t)e * INTER + (size_t)nb * 64) * (2 * HID);
    const bf16* gP = g_wgp + wo;
    const bf16* uP = g_wup + wo;

    GuAcc A = {};
    const int wm = wid & 3, wn = wid >> 2;
    const int rsel = lane & 15, csel = ((lane >> 4) << 4);

    const int KT = HID / 32;
    for (int kt = 0; kt < KT; ++kt) {
        __syncthreads();
        tile_async<128>(sb,         aP + kt * 64, 2 * HID, tid);
        tile_async<64>(sb + 16384,  gP + kt * 64, 2 * HID, tid);
        tile_async<64>(sb + 24576,  uP + kt * 64, 2 * HID, tid);
        CP_COMMIT(); CP_WAIT0();
        __syncthreads();
        gu_compute(A, sb, sb + 16384, sb + 24576, wm, wn, rsel, csel);
    }
    gu_epilogue(A, mb, nb, wm, wn, lane);
}

// =========================== DOWN compute + epilogue (shared) ======================
struct DnAcc { float a[2][8][4]; };

__device__ __forceinline__ void dn_compute(DnAcc& A, uint32_t sbA, uint32_t sbB,
                                           int wm, int wn, int rsel, int csel) {
#pragma unroll
    for (int ks = 0; ks < 2; ks++) {
        const int ch = ks * 32 + csel;
        uint32_t ah[2][4], al[2][4];
#pragma unroll
        for (int mt = 0; mt < 2; mt++) {
            uint32_t ro = (wm * 32 + mt * 16 + rsel) * 128;
            LDM_X4(ah[mt], sbA + SWZ(ro + ch));
            LDM_X4(al[mt], sbA + SWZ(ro + ch + 64));
        }
#pragma unroll
        for (int g = 0; g < 4; g++) {
            uint32_t ro = (wn * 64 + g * 16 + rsel) * 128;
            uint32_t bh[4], bl[4];
            LDM_X4(bh, sbB + SWZ(ro + ch));
            LDM_X4(bl, sbB + SWZ(ro + ch + 64));
#pragma unroll
            for (int mt = 0; mt < 2; mt++)
#pragma unroll
            for (int t = 0; t < 2; t++) {
                const int nt = g * 2 + t;
                mma16816(A.a[mt][nt], ah[mt], bh[t], bh[t + 2]);
                mma16816(A.a[mt][nt], ah[mt], bl[t], bl[t + 2]);
                mma16816(A.a[mt][nt], al[mt], bh[t], bh[t + 2]);
            }
        }
    }
}

__device__ __forceinline__ void dn_epilogue(DnAcc& A, int mb, int nb, int wm, int wn, int lane) {
#pragma unroll
    for (int mt = 0; mt < 2; mt++)
#pragma unroll
    for (int nt = 0; nt < 8; nt++)
#pragma unroll
    for (int h = 0; h < 2; h++) {
        int row = mb * 128 + wm * 32 + mt * 16 + (lane >> 2) + h * 8;
        int col = nb * 128 + wn * 64 + nt * 8 + (lane & 3) * 2;
        float2 v = { A.a[mt][nt][h * 2], A.a[mt][nt][h * 2 + 1] };
        *(float2*)&g_oute[(size_t)row * HID + col] = v;
    }
}

// ---- pipelined down (3-stage, 96KB dynamic smem) ----
#define DN_STG 32768
__global__ __launch_bounds__(256) void gemm_dn_pipe() {
    extern __shared__ char smem[];
    const uint32_t sb = smem_to_u32(smem);
    const int tid = threadIdx.x, wid = tid >> 5, lane = tid & 31;
    const int nb = blockIdx.x, mb = blockIdx.y;
    const int e = mb >> 4;

    const bf16* aP = g_intp + (size_t)mb * 128 * (2 * INTER);
    const bf16* bP = g_wdp + ((size_t)e * HID + (size_t)nb * 128) * (2 * INTER);

    DnAcc A = {};
    const int wm = wid & 3, wn = wid >> 2;
    const int rsel = lane & 15, csel = ((lane >> 4) << 4);

    auto load_stage = [&](int kt) {
        uint32_t base = sb + (kt % 3) * DN_STG;
        tile_async<128>(base,         aP + kt * 64, 2 * INTER, tid);
        tile_async<128>(base + 16384, bP + kt * 64, 2 * INTER, tid);
        CP_COMMIT();
    };

    const int KT = INTER / 32;  // 128
    load_stage(0);
    load_stage(1);
#pragma unroll 1
    for (int kt = 0; kt < KT; ++kt) {
        CP_WAIT1();
        __syncthreads();
        if (kt + 2 < KT) load_stage(kt + 2);
        uint32_t base = sb + (kt % 3) * DN_STG;
        dn_compute(A, base, base + 16384, wm, wn, rsel, csel);
    }
    dn_epilogue(A, mb, nb, wm, wn, lane);
}

// ---- fallback single-stage down (passing R14 version, static smem) ----
__global__ __launch_bounds__(256) void gemm_dn_mma() {
    __shared__ char smem[32768];
    const uint32_t sb = smem_to_u32(smem);
    const int tid = threadIdx.x, wid = tid >> 5, lane = tid & 31;
    const int nb = blockIdx.x, mb = blockIdx.y;
    const int e = mb >> 4;

    const bf16* aP = g_intp + (size_t)mb * 128 * (2 * INTER);
    const bf16* bP = g_wdp + ((size_t)e * HID + (size_t)nb * 128) * (2 * INTER);

    DnAcc A = {};
    const int wm = wid & 3, wn = wid >> 2;
    const int rsel = lane & 15, csel = ((lane >> 4) << 4);

    const int KT = INTER / 32;
#pragma unroll 1
    for (int kt = 0; kt < KT; ++kt) {
        __syncthreads();
        tile_async<128>(sb,         aP + kt * 64, 2 * INTER, tid);
        tile_async<128>(sb + 16384, bP + kt * 64, 2 * INTER, tid);
        CP_COMMIT(); CP_WAIT0();
        __syncthreads();
        dn_compute(A, sb, sb + 16384, wm, wn, rsel, csel);
    }
    dn_epilogue(A, mb, nb, wm, wn, lane);
}

// ---------------- combine (validated) ----------------------------------------------
__global__ void combine_kernel(float* __restrict__ out) {
    int t = blockIdx.x;
    int h = threadIdx.x * 4;
    int p0 = g_perm[2 * t], p1 = g_perm[2 * t + 1];
    float a0 = g_affw[2 * t], a1 = g_affw[2 * t + 1];
    float4 v0 = *(const float4*)(g_oute + (size_t)p0 * HID + h);
    float4 v1 = *(const float4*)(g_oute + (size_t)p1 * HID + h);
    float4 r;
    r.x = a0 * v0.x + a1 * v1.x;
    r.y = a0 * v0.y + a1 * v1.y;
    r.z = a0 * v0.z + a1 * v1.z;
    r.w = a0 * v0.w + a1 * v1.w;
    *(float4*)(out + (size_t)t * HID + h) = r;
}

// ---------------- launch ------------------------------------------------------------
extern "C" void kernel_launch(void* const* d_in, const int* in_sizes, int n_in,
                              void* d_out, int out_size) {
    const float* hidden = (const float*)d_in[0];
    const float* aff    = (const float*)d_in[1];
    const float* gate_w = (const float*)d_in[2];
    const float* up_w   = (const float*)d_in[3];
    const float* down_w = (const float*)d_in[4];
    const int*   eidx   = (const int*)d_in[5];
    float* out = (float*)d_out;

    // Opt into 96KB dynamic smem for the pipelined kernels; fall back to the
    // validated single-stage kernels if the attribute is rejected (deterministic).
    cudaError_t e1 = cudaFuncSetAttribute(gemm_gu_pipe,
        cudaFuncAttributeMaxDynamicSharedMemorySize, 3 * GU_STG);
    cudaError_t e2 = cudaFuncSetAttribute(gemm_dn_pipe,
        cudaFuncAttributeMaxDynamicSharedMemorySize, 3 * DN_STG);
    const bool pipe_ok = (e1 == cudaSuccess) && (e2 == cudaSuccess);

    route_kernel<<<1, 256>>>(eidx, aff);
    gather_split_kernel<<<SLOTS, 256>>>(hidden);
    transpose_split_kernel<<<dim3(INTER / 32, HID / 32, NEXP), 256>>>(gate_w, 0, HID, INTER);
    transpose_split_kernel<<<dim3(INTER / 32, HID / 32, NEXP), 256>>>(up_w,   1, HID, INTER);
    transpose_split_kernel<<<dim3(HID / 32, INTER / 32, NEXP), 256>>>(down_w, 2, INTER, HID);

    if (pipe_ok) {
        gemm_gu_pipe<<<dim3(INTER / 64, SLOTS / 128), 256, 3 * GU_STG>>>();
        gemm_dn_pipe<<<dim3(HID / 128, SLOTS / 128), 256, 3 * DN_STG>>>();
    } else {
        gemm_gu_mma<<<dim3(INTER / 64, SLOTS / 128), 256>>>();
        gemm_dn_mma<<<dim3(HID / 128, SLOTS / 128), 256>>>();
    }

    combine_kernel<<<TOKENS, 256>>>(out);
}